// round 10
// baseline (speedup 1.0000x reference)
#include <cuda_runtime.h>
#include <cuda_bf16.h>
#include <math.h>
#include <stdint.h>

// ------------------------- problem constants -------------------------
#define N_TOK 32768
#define D     256
#define E     8
#define H     1024

#define BM 128          // tokens per expert CTA
#define THREADS 256     // 8 warps: 2 (m) x 4 (n)
#define NSLOT 3
#define NSLAB 128       // 16 hc x (4 W1 + 4 W2) slabs

// ---- fused-kernel SMEM map (bytes) ----
// x  : [128 rows x 512 B] hi + lo            (131072)
// h  : [128 rows x 128 B] hi + lo            ( 32768)
// ring: 3 slots x 16384 (8K hi + 8K lo)      ( 49152)
// meta: stok[128], swgt[128]
#define SX      0
#define SX_LO   65536
#define SH      131072
#define SH_LO   (SH + 16384)
#define SSLAB   163840
#define SMETA2  (SSLAB + NSLOT * 16384)      // 212992
#define SMEM2   (SMETA2 + 1024)

// ------------------------- static scratch -----------------------------
__device__ int            g_cnt[E];
__device__ int            g_tok[E * N_TOK];
__device__ float          g_wgt[E * N_TOK];
__device__ __nv_bfloat16  g_xh[N_TOK * D];
__device__ __nv_bfloat16  g_xl[N_TOK * D];
__device__ __nv_bfloat16  g_w1h[E * H * D];     // [e][n=H][k=D]
__device__ __nv_bfloat16  g_w1l[E * H * D];
__device__ __nv_bfloat16  g_w2h[E * D * H];     // [e][n=D][k=H]
__device__ __nv_bfloat16  g_w2l[E * D * H];

// ------------------------- small helpers ------------------------------
__device__ __forceinline__ uint32_t smem_u32(const void* p) {
    uint32_t a;
    asm("{ .reg .u64 t; cvta.to.shared.u64 t, %1; cvt.u32.u64 %0, t; }"
        : "=r"(a) : "l"(p));
    return a;
}
__device__ __forceinline__ void ldm4(uint32_t* r, uint32_t addr) {
    asm volatile("ldmatrix.sync.aligned.m8n8.x4.shared.b16 {%0,%1,%2,%3}, [%4];"
                 : "=r"(r[0]), "=r"(r[1]), "=r"(r[2]), "=r"(r[3]) : "r"(addr));
}
__device__ __forceinline__ void mma16816(float* c, const uint32_t* a,
                                         uint32_t b0, uint32_t b1) {
    asm volatile("mma.sync.aligned.m16n8k16.row.col.f32.bf16.bf16.f32 "
                 "{%0,%1,%2,%3}, {%4,%5,%6,%7}, {%8,%9}, {%0,%1,%2,%3};"
                 : "+f"(c[0]), "+f"(c[1]), "+f"(c[2]), "+f"(c[3])
                 : "r"(a[0]), "r"(a[1]), "r"(a[2]), "r"(a[3]), "r"(b0), "r"(b1));
}
__device__ __forceinline__ void cpa16(uint32_t dst, const void* src) {
    asm volatile("cp.async.cg.shared.global [%0], [%1], 16;" :: "r"(dst), "l"(src));
}
#define CP_COMMIT() asm volatile("cp.async.commit_group;" ::: "memory")
#define CP_WAIT(n)  asm volatile("cp.async.wait_group %0;" :: "n"(n) : "memory")

__device__ __forceinline__ float gelu_exact(float v) {
    return 0.5f * v * (1.f + erff(v * 0.70710678118654752f));
}

// swizzled physical addresses (16B-granular XOR, conflict-free ldmatrix)
__device__ __forceinline__ uint32_t xaddr(uint32_t b, int row, int kb) {   // 512B rows
    return b + row * 512 + (((kb >> 4) ^ (row & 7)) << 4);
}
__device__ __forceinline__ uint32_t haddr(uint32_t b, int row, int kb) {   // 128B rows
    return b + row * 128 + (((kb >> 4) ^ (row & 7)) << 4) + (kb & 15);
}
__device__ __forceinline__ uint32_t w2addr(uint32_t b, int row, int kb) {  // 64B rows
    return b + row * 64 + (((kb >> 4) ^ ((row >> 1) & 3)) << 4);
}

// ------------------------- prep kernels -------------------------------
__global__ void prep_x_kernel(const float* __restrict__ x, float* __restrict__ out) {
    int i = blockIdx.x * blockDim.x + threadIdx.x;
    if (i < E) g_cnt[i] = 0;
    if (i >= (N_TOK * D) / 4) return;
    ((float4*)out)[i] = make_float4(0.f, 0.f, 0.f, 0.f);
    float4 v = ((const float4*)x)[i];
    __nv_bfloat16 h0 = __float2bfloat16_rn(v.x), h1 = __float2bfloat16_rn(v.y);
    __nv_bfloat16 h2 = __float2bfloat16_rn(v.z), h3 = __float2bfloat16_rn(v.w);
    __nv_bfloat16 l0 = __float2bfloat16_rn(v.x - __bfloat162float(h0));
    __nv_bfloat16 l1 = __float2bfloat16_rn(v.y - __bfloat162float(h1));
    __nv_bfloat16 l2 = __float2bfloat16_rn(v.z - __bfloat162float(h2));
    __nv_bfloat16 l3 = __float2bfloat16_rn(v.w - __bfloat162float(h3));
    __nv_bfloat162* ph = (__nv_bfloat162*)g_xh;
    __nv_bfloat162* pl = (__nv_bfloat162*)g_xl;
    __nv_bfloat162 a, b;
    a.x = h0; a.y = h1; b.x = h2; b.y = h3;
    ph[2 * i] = a; ph[2 * i + 1] = b;
    a.x = l0; a.y = l1; b.x = l2; b.y = l3;
    pl[2 * i] = a; pl[2 * i + 1] = b;
}

__global__ void w1t_kernel(const float* __restrict__ W1) {
    __shared__ float tile[32][33];
    int e = blockIdx.z;
    int nb = blockIdx.x * 32, kb = blockIdx.y * 32;
    int tx = threadIdx.x, ty = threadIdx.y;
    for (int r = ty; r < 32; r += 8)
        tile[r][tx] = W1[(size_t)e * D * H + (size_t)(kb + r) * H + nb + tx];
    __syncthreads();
    for (int r = ty; r < 32; r += 8) {
        float v = tile[tx][r];
        __nv_bfloat16 hi = __float2bfloat16_rn(v);
        __nv_bfloat16 lo = __float2bfloat16_rn(v - __bfloat162float(hi));
        size_t o = ((size_t)e * H + nb + r) * D + kb + tx;
        g_w1h[o] = hi; g_w1l[o] = lo;
    }
}

__global__ void w2t_kernel(const float* __restrict__ W2) {
    __shared__ float tile[32][33];
    int e = blockIdx.z;
    int nb = blockIdx.x * 32, kb = blockIdx.y * 32;
    int tx = threadIdx.x, ty = threadIdx.y;
    for (int r = ty; r < 32; r += 8)
        tile[r][tx] = W2[(size_t)e * H * D + (size_t)(kb + r) * D + nb + tx];
    __syncthreads();
    for (int r = ty; r < 32; r += 8) {
        float v = tile[tx][r];
        __nv_bfloat16 hi = __float2bfloat16_rn(v);
        __nv_bfloat16 lo = __float2bfloat16_rn(v - __bfloat162float(hi));
        size_t o = ((size_t)e * D + nb + r) * H + kb + tx;
        g_w2h[o] = hi; g_w2l[o] = lo;
    }
}

// ------------------------- router (tiled SMEM) -------------------------
#define RT_TOK 32
#define RT_XS  260
__global__ void __launch_bounds__(256) router_kernel(
    const float* __restrict__ x,
    const float* __restrict__ grad,
    const float* __restrict__ Wr,
    const float* __restrict__ br,
    float* __restrict__ probs_out)
{
    __shared__ float xs[RT_TOK * RT_XS];
    __shared__ float wr[(D + 1) * E];
    __shared__ float sbr[E];
    __shared__ float lg[RT_TOK * E];

    int t = threadIdx.x;
    int base = blockIdx.x * RT_TOK;

    for (int i = t; i < RT_TOK * (D / 4); i += 256) {
        int row = i >> 6, c = i & 63;
        float4 v = ((const float4*)(x + (size_t)(base + row) * D))[c];
        float* dst = xs + row * RT_XS + c * 4;
        dst[0] = v.x; dst[1] = v.y; dst[2] = v.z; dst[3] = v.w;
    }
    for (int i = t; i < (D + 1) * E / 2; i += 256)
        ((float2*)wr)[i] = ((const float2*)Wr)[i];
    if (t < E) sbr[t] = br[t];
    __syncthreads();

    {
        int tok = t >> 3, e = t & 7;
        const float* xr = xs + tok * RT_XS;
        float acc = 0.f;
#pragma unroll 8
        for (int d = 0; d < D; d++)
            acc = fmaf(xr[d], wr[d * E + e], acc);
        acc += grad[base + tok] * wr[D * E + e] + sbr[e];
        lg[tok * E + e] = acc;
    }
    __syncthreads();

    if (t < RT_TOK) {
        int n = base + t;
        float p[E]; float mx = -1e30f;
#pragma unroll
        for (int e = 0; e < E; e++) { p[e] = lg[t * E + e]; mx = fmaxf(mx, p[e]); }
        float s = 0.f;
#pragma unroll
        for (int e = 0; e < E; e++) { p[e] = expf(p[e] - mx); s += p[e]; }
        float inv = 1.f / s;
#pragma unroll
        for (int e = 0; e < E; e++) p[e] *= inv;
        float4* po = (float4*)(probs_out + (size_t)n * E);
        po[0] = make_float4(p[0], p[1], p[2], p[3]);
        po[1] = make_float4(p[4], p[5], p[6], p[7]);

        int i1 = 0; float v1 = p[0];
#pragma unroll
        for (int e = 1; e < E; e++) if (p[e] > v1) { v1 = p[e]; i1 = e; }
        int i2 = -1; float v2 = -1.f;
#pragma unroll
        for (int e = 0; e < E; e++) if (e != i1 && p[e] > v2) { v2 = p[e]; i2 = e; }

        int s1 = atomicAdd(&g_cnt[i1], 1);
        g_tok[i1 * N_TOK + s1] = n; g_wgt[i1 * N_TOK + s1] = v1;
        int s2 = atomicAdd(&g_cnt[i2], 1);
        g_tok[i2 * N_TOK + s2] = n; g_wgt[i2 * N_TOK + s2] = v2;
    }
}

// ---------------- fused expert kernel pieces ---------------------------
// stage one 16KB ring slab (W1 slab: [64n x 64k]; W2 slab: [128n x 32k])
__device__ __forceinline__ void stage_slab2(uint32_t su, int t, int e, int tt) {
    int hc = tt >> 3, r = tt & 7;
    uint32_t slot = su + SSLAB + (tt % NSLOT) * 16384;
    if (r < 4) {
#pragma unroll
        for (int rep = 0; rep < 2; rep++) {
            int i = t + rep * THREADS;           // 0..511
            int row = i >> 3, q = i & 7;
            uint32_t d = slot + row * 128 + ((q ^ (row & 7)) << 4);
            size_t s = ((size_t)(e * H + hc * 64 + row)) * D + r * 64 + q * 8;
            cpa16(d, g_w1h + s);
            cpa16(d + 8192, g_w1l + s);
        }
    } else {
        int half = (r - 4) >> 1, kc2 = (r - 4) & 1;
#pragma unroll
        for (int rep = 0; rep < 2; rep++) {
            int i = t + rep * THREADS;
            int row = i >> 2, q = i & 3;
            uint32_t d = slot + row * 64 + ((q ^ ((row >> 1) & 3)) << 4);
            size_t s = ((size_t)(e * D + half * 128 + row)) * H + hc * 64 + kc2 * 32 + q * 8;
            cpa16(d, g_w2h + s);
            cpa16(d + 8192, g_w2l + s);
        }
    }
}

// GEMM1 over one W1 slab (kc = r*64 of K=256), hi/lo x3 passes
__device__ __forceinline__ void mma_w1(uint32_t su, uint32_t slot, int r,
                                       int wm, int wn, int l, float acc1[4][2][4]) {
#pragma unroll
    for (int k16 = 0; k16 < 4; k16++) {
        int arow = wm * 64 + (l & 15);
        int akb = (r * 64 + k16 * 16 + ((l >> 4) & 1) * 8) * 2;   // byte in x row
        int brow = wn * 16 + (l & 7) + ((l >> 4) & 1) * 8;        // n-row in slab
        int bkb = (k16 * 16 + ((l >> 3) & 1) * 8) * 2;            // byte in slab row

        uint32_t ah[4][4], bh4[4];
#pragma unroll
        for (int mi = 0; mi < 4; mi++)
            ldm4(ah[mi], xaddr(su + SX, arow + mi * 16, akb));
        ldm4(bh4, haddr(slot, brow, bkb));
#pragma unroll
        for (int mi = 0; mi < 4; mi++)
#pragma unroll
            for (int ni = 0; ni < 2; ni++)
                mma16816(acc1[mi][ni], ah[mi], bh4[ni * 2], bh4[ni * 2 + 1]);
        {
            uint32_t bl4[4];
            ldm4(bl4, haddr(slot + 8192, brow, bkb));
#pragma unroll
            for (int mi = 0; mi < 4; mi++)
#pragma unroll
                for (int ni = 0; ni < 2; ni++)
                    mma16816(acc1[mi][ni], ah[mi], bl4[ni * 2], bl4[ni * 2 + 1]);
        }
        {
            uint32_t al[4][4];
#pragma unroll
            for (int mi = 0; mi < 4; mi++)
                ldm4(al[mi], xaddr(su + SX_LO, arow + mi * 16, akb));
#pragma unroll
            for (int mi = 0; mi < 4; mi++)
#pragma unroll
                for (int ni = 0; ni < 2; ni++)
                    mma16816(acc1[mi][ni], al[mi], bh4[ni * 2], bh4[ni * 2 + 1]);
        }
    }
}

// GEMM2 over one W2 slab (k = kc2*32 within hc's 64), hi/lo x3
__device__ __forceinline__ void mma_w2(uint32_t su, uint32_t slot, int kc2,
                                       int wm, int wn, int l, float acc[4][4][4]) {
#pragma unroll
    for (int k16 = 0; k16 < 2; k16++) {
        int arow = wm * 64 + (l & 15);
        int akb = (kc2 * 32 + k16 * 16 + ((l >> 4) & 1) * 8) * 2;  // byte in h row
        int brow0 = wn * 32 + (l & 7) + ((l >> 4) & 1) * 8;
        int bkb = (k16 * 16 + ((l >> 3) & 1) * 8) * 2;             // byte in W2 row

        uint32_t ah[4][4], bh[2][4];
#pragma unroll
        for (int mi = 0; mi < 4; mi++)
            ldm4(ah[mi], haddr(su + SH, arow + mi * 16, akb));
#pragma unroll
        for (int nh = 0; nh < 2; nh++)
            ldm4(bh[nh], w2addr(slot, brow0 + nh * 16, bkb));
#pragma unroll
        for (int mi = 0; mi < 4; mi++)
#pragma unroll
            for (int ni = 0; ni < 4; ni++)
                mma16816(acc[mi][ni], ah[mi],
                         bh[ni >> 1][(ni & 1) * 2], bh[ni >> 1][(ni & 1) * 2 + 1]);
        {
            uint32_t bl[2][4];
#pragma unroll
            for (int nh = 0; nh < 2; nh++)
                ldm4(bl[nh], w2addr(slot + 8192, brow0 + nh * 16, bkb));
#pragma unroll
            for (int mi = 0; mi < 4; mi++)
#pragma unroll
                for (int ni = 0; ni < 4; ni++)
                    mma16816(acc[mi][ni], ah[mi],
                             bl[ni >> 1][(ni & 1) * 2], bl[ni >> 1][(ni & 1) * 2 + 1]);
        }
        {
            uint32_t al[4][4];
#pragma unroll
            for (int mi = 0; mi < 4; mi++)
                ldm4(al[mi], haddr(su + SH_LO, arow + mi * 16, akb));
#pragma unroll
            for (int mi = 0; mi < 4; mi++)
#pragma unroll
                for (int ni = 0; ni < 4; ni++)
                    mma16816(acc[mi][ni], al[mi],
                             bh[ni >> 1][(ni & 1) * 2], bh[ni >> 1][(ni & 1) * 2 + 1]);
        }
    }
}

// ------------------------- fused expert kernel -------------------------
__global__ void __launch_bounds__(THREADS, 1) moe_kernel(
    const float* __restrict__ b1, const float* __restrict__ b2,
    float* __restrict__ out)
{
    int e = blockIdx.y;
    int cnt = g_cnt[e];
    int base = blockIdx.x * BM;
    if (base >= cnt) return;

    extern __shared__ char smem[];
    const uint32_t su = smem_u32(smem);
    int*   stok = (int*)(smem + SMETA2);
    float* swgt = (float*)(smem + SMETA2 + 512);

    int t = threadIdx.x;
    int wid = t >> 5, l = t & 31;
    int wm = wid >> 2, wn = wid & 3;

    if (t < BM) {
        int idx = base + t;
        stok[t] = (idx < cnt) ? g_tok[e * N_TOK + idx] : 0;
        swgt[t] = (idx < cnt) ? g_wgt[e * N_TOK + idx] : 0.f;
    }
    __syncthreads();

    // stage resident x (hi+lo), one commit group
#pragma unroll
    for (int rep = 0; rep < 16; rep++) {
        int i = t + rep * THREADS;               // 0..4095
        int row = i >> 5, q = i & 31;
        uint32_t d = su + SX + row * 512 + ((q ^ (row & 7)) << 4);
        size_t s = (size_t)stok[row] * D + q * 8;
        cpa16(d, g_xh + s);
        cpa16(d + SX_LO, g_xl + s);
    }
    CP_COMMIT();
    stage_slab2(su, t, e, 0); CP_COMMIT();
    stage_slab2(su, t, e, 1); CP_COMMIT();

    float acc2[2][4][4][4];
#pragma unroll
    for (int hf = 0; hf < 2; hf++)
#pragma unroll
        for (int mi = 0; mi < 4; mi++)
#pragma unroll
            for (int ni = 0; ni < 4; ni++)
#pragma unroll
                for (int c = 0; c < 4; c++) acc2[hf][mi][ni][c] = 0.f;

    int tt = 0;
#pragma unroll 1
    for (int hc = 0; hc < 16; hc++) {            // FIX: 16 chunks cover H=1024
        float acc1[4][2][4];
#pragma unroll
        for (int mi = 0; mi < 4; mi++)
#pragma unroll
            for (int ni = 0; ni < 2; ni++)
#pragma unroll
                for (int c = 0; c < 4; c++) acc1[mi][ni][c] = 0.f;

        // ---- GEMM1: 4 W1 slabs over K=256 ----
#pragma unroll
        for (int j = 0; j < 4; j++) {
            if (tt < NSLAB - 2) { CP_WAIT(1); } else { CP_WAIT(0); }
            __syncthreads();
            uint32_t slot = su + SSLAB + (tt % NSLOT) * 16384;
            mma_w1(su, slot, j, wm, wn, l, acc1);
            if (tt + 2 < NSLAB) { stage_slab2(su, t, e, tt + 2); CP_COMMIT(); }
            tt++;
        }

        // ---- h = gelu(acc1 + b1) -> SMEM hi/lo ----
        {
            const float* b1e = b1 + e * H + hc * 64;
#pragma unroll
            for (int mi = 0; mi < 4; mi++) {
#pragma unroll
                for (int ni = 0; ni < 2; ni++) {
                    int col = wn * 16 + ni * 8 + (l & 3) * 2;
                    float ba = b1e[col], bb = b1e[col + 1];
#pragma unroll
                    for (int hf = 0; hf < 2; hf++) {
                        int row = wm * 64 + mi * 16 + (l >> 2) + hf * 8;
                        float g0 = gelu_exact(acc1[mi][ni][hf * 2 + 0] + ba);
                        float g1 = gelu_exact(acc1[mi][ni][hf * 2 + 1] + bb);
                        __nv_bfloat16 h0 = __float2bfloat16_rn(g0);
                        __nv_bfloat16 h1 = __float2bfloat16_rn(g1);
                        __nv_bfloat16 l0 = __float2bfloat16_rn(g0 - __bfloat162float(h0));
                        __nv_bfloat16 l1 = __float2bfloat16_rn(g1 - __bfloat162float(h1));
                        int kb = col * 2;
                        uint32_t off = (uint32_t)(row * 128 +
                                       (((kb >> 4) ^ (row & 7)) << 4) + (kb & 15));
                        __nv_bfloat162 hp, lp;
                        hp.x = h0; hp.y = h1; lp.x = l0; lp.y = l1;
                        *(__nv_bfloat162*)(smem + SH + off) = hp;
                        *(__nv_bfloat162*)(smem + SH + 16384 + off) = lp;
                    }
                }
            }
        }
        // (next slab iteration's __syncthreads orders h writes before reads)

        // ---- GEMM2: 4 W2 slabs (2 halves x 2 k-chunks) ----
#pragma unroll
        for (int j = 0; j < 4; j++) {
            if (tt < NSLAB - 2) { CP_WAIT(1); } else { CP_WAIT(0); }
            __syncthreads();
            uint32_t slot = su + SSLAB + (tt % NSLOT) * 16384;
            mma_w2(su, slot, j & 1, wm, wn, l, acc2[j >> 1]);
            if (tt + 2 < NSLAB) { stage_slab2(su, t, e, tt + 2); CP_COMMIT(); }
            tt++;
        }
    }

    // ---- epilogue: out[token] += w * (acc2 + b2) ----
    const float* b2e = b2 + e * D;
#pragma unroll
    for (int hf = 0; hf < 2; hf++) {
#pragma unroll
        for (int mi = 0; mi < 4; mi++) {
#pragma unroll
            for (int ch = 0; ch < 2; ch++) {
                int m = wm * 64 + mi * 16 + (l >> 2) + ch * 8;
                float w = swgt[m];
                if (w == 0.f) continue;
                int tok = stok[m];
                float* op = out + (size_t)tok * D;
#pragma unroll
                for (int ni = 0; ni < 4; ni++) {
                    int col = hf * 128 + wn * 32 + ni * 8 + (l & 3) * 2;
                    atomicAdd(op + col,     w * (acc2[hf][mi][ni][ch * 2 + 0] + b2e[col]));
                    atomicAdd(op + col + 1, w * (acc2[hf][mi][ni][ch * 2 + 1] + b2e[col + 1]));
                }
            }
        }
    }
}

// --------------------------------- launch --------------------------------
extern "C" void kernel_launch(void* const* d_in, const int* in_sizes, int n_in,
                              void* d_out, int out_size) {
    const float* x    = (const float*)d_in[0];
    const float* grad = (const float*)d_in[1];
    const float* Wr   = (const float*)d_in[2];
    const float* br   = (const float*)d_in[3];
    const float* W1   = (const float*)d_in[4];
    const float* b1   = (const float*)d_in[5];
    const float* W2   = (const float*)d_in[6];
    const float* b2   = (const float*)d_in[7];

    float* out   = (float*)d_out;                       // [N, D]
    float* probs = (float*)d_out + (size_t)N_TOK * D;   // [N, E]

    static int attr_set = 0;
    if (!attr_set) {
        cudaFuncSetAttribute(moe_kernel,
                             cudaFuncAttributeMaxDynamicSharedMemorySize, SMEM2);
        attr_set = 1;
    }

    prep_x_kernel<<<(N_TOK * D / 4 + 255) / 256, 256>>>(x, out);
    {
        dim3 g(H / 32, D / 32, E), b(32, 8);
        w1t_kernel<<<g, b>>>(W1);
    }
    {
        dim3 g(D / 32, H / 32, E), b(32, 8);
        w2t_kernel<<<g, b>>>(W2);
    }
    router_kernel<<<N_TOK / RT_TOK, 256>>>(x, grad, Wr, br, probs);
    {
        dim3 grid(N_TOK / BM, E);   // (256, 8), early-exit on cnt
        moe_kernel<<<grid, THREADS, SMEM2>>>(b1, b2, out);
    }
}